// round 3
// baseline (speedup 1.0000x reference)
#include <cuda_runtime.h>

// ---------------------------------------------------------------------------
// Problem constants
// ---------------------------------------------------------------------------
namespace {
constexpr int kB  = 8;
constexpr int kN  = 512;
constexpr int kS  = 96;
constexpr int kH  = 256;
constexpr int kNH = 8;
constexpr int kHD = 32;
constexpr int kOUT = 4;
constexpr int MQ = kB * kN;   // 4096 query rows
constexpr int MT = kB * kS;   // 768 temporal rows
}

// ---------------------------------------------------------------------------
// Scratch (device globals — no allocation allowed)
// ---------------------------------------------------------------------------
__device__ __align__(16) float g_Wqs[kH * kH];       // Wq @ Ws
__device__ __align__(16) float g_W1ao[kH * kH];      // W1 @ Wao
__device__ __align__(16) float g_bqs[kH];
__device__ __align__(16) float g_b1ao[kH];
__device__ __align__(16) float g_q[MQ * kH];
__device__ __align__(16) float g_tp[MT * kH];
__device__ __align__(16) float g_kv[MT * 2 * kH];    // [.. ,0:256]=k, [..,256:512]=v
__device__ __align__(16) float g_ctx[MQ * kH];
__device__ __align__(16) float g_fused[MQ * kH];
__device__ __align__(16) float g_h2[MQ * (kH / 2)];
__device__ __align__(16) float g_y[MQ * kOUT];

// ---------------------------------------------------------------------------
// Register-tiled SGEMM body: C[M,N] = A[M,K] @ op(B) + bias, optional ReLU
//   BT = true :  op(B) = B^T with B stored row-major [N,K]   (NT)
//   BT = false:  op(B) = B   with B stored row-major [K,N]   (NN)
// 64x64 block tile, BK=16, 256 threads, 4x4 per thread.
// Requires M%64==0, N%64==0, K%16==0 (all call sites satisfy this).
// ---------------------------------------------------------------------------
template <bool BT, bool RELU>
__device__ __forceinline__ void gemm_body(
    const float* __restrict__ A, const float* __restrict__ Bm,
    const float* __restrict__ bias, float* __restrict__ C,
    int M, int N, int K, int bx, int by)
{
    __shared__ float As[16][64];
    __shared__ float Bs[16][64];

    const int tid = threadIdx.x;
    const int tx  = tid & 15;
    const int ty  = tid >> 4;
    const int m0  = by * 64;
    const int n0  = bx * 64;

    // global->smem load mapping
    const int aRow = tid >> 2;          // 0..63
    const int aK   = (tid & 3) << 2;    // 0,4,8,12
    const int bKnn = tid >> 4;          // 0..15   (NN)
    const int bNnn = (tid & 15) << 2;   // 0..60   (NN)

    const float* Aptr = A + (m0 + aRow) * K + aK;
    const float* Bptr = BT ? (Bm + (n0 + aRow) * K + aK)
                           : (Bm + bKnn * N + n0 + bNnn);
    const int Bstep = BT ? 16 : 16 * N;

    float acc[4][4];
#pragma unroll
    for (int i = 0; i < 4; i++)
#pragma unroll
        for (int j = 0; j < 4; j++) acc[i][j] = 0.f;

    float4 aR = *(const float4*)Aptr;
    float4 bR = *(const float4*)Bptr;

    for (int k0 = 0;;) {
        // stage regs -> smem
        As[aK + 0][aRow] = aR.x;
        As[aK + 1][aRow] = aR.y;
        As[aK + 2][aRow] = aR.z;
        As[aK + 3][aRow] = aR.w;
        if (BT) {
            Bs[aK + 0][aRow] = bR.x;
            Bs[aK + 1][aRow] = bR.y;
            Bs[aK + 2][aRow] = bR.z;
            Bs[aK + 3][aRow] = bR.w;
        } else {
            *(float4*)&Bs[bKnn][bNnn] = bR;
        }
        __syncthreads();

        k0 += 16;
        const bool nxt = k0 < K;
        float4 aN = make_float4(0.f, 0.f, 0.f, 0.f);
        float4 bN = make_float4(0.f, 0.f, 0.f, 0.f);
        if (nxt) {
            Aptr += 16;
            Bptr += Bstep;
            aN = *(const float4*)Aptr;
            bN = *(const float4*)Bptr;
        }

#pragma unroll
        for (int kk = 0; kk < 16; kk++) {
            const float4 av = *(const float4*)&As[kk][ty << 2];
            const float4 bv = *(const float4*)&Bs[kk][tx << 2];
            const float a[4] = {av.x, av.y, av.z, av.w};
            const float b[4] = {bv.x, bv.y, bv.z, bv.w};
#pragma unroll
            for (int i = 0; i < 4; i++)
#pragma unroll
                for (int j = 0; j < 4; j++) acc[i][j] += a[i] * b[j];
        }

        if (!nxt) break;
        __syncthreads();
        aR = aN;
        bR = bN;
    }

    float bv[4] = {0.f, 0.f, 0.f, 0.f};
    if (bias) {
        const float4 t = *(const float4*)&bias[n0 + (tx << 2)];
        bv[0] = t.x; bv[1] = t.y; bv[2] = t.z; bv[3] = t.w;
    }
#pragma unroll
    for (int i = 0; i < 4; i++) {
        const int row = m0 + (ty << 2) + i;
        float4 o;
        o.x = acc[i][0] + bv[0];
        o.y = acc[i][1] + bv[1];
        o.z = acc[i][2] + bv[2];
        o.w = acc[i][3] + bv[3];
        if (RELU) {
            o.x = fmaxf(o.x, 0.f);
            o.y = fmaxf(o.y, 0.f);
            o.z = fmaxf(o.z, 0.f);
            o.w = fmaxf(o.w, 0.f);
        }
        *(float4*)&C[row * N + n0 + (tx << 2)] = o;
    }
}

template <bool BT, bool RELU>
__global__ void __launch_bounds__(256) gemm_k(
    const float* __restrict__ A, const float* __restrict__ Bm,
    const float* __restrict__ bias, float* __restrict__ C,
    int M, int N, int K)
{
    gemm_body<BT, RELU>(A, Bm, bias, C, M, N, K, blockIdx.x, blockIdx.y);
}

// Both weight composes (Wq@Ws and W1@Wao) in one launch via blockIdx.z.
__global__ void __launch_bounds__(256) compose_k(
    const float* __restrict__ Win, const float* __restrict__ Ws,
    const float* __restrict__ W1,  const float* __restrict__ Wao)
{
    const float* A  = blockIdx.z ? W1  : Win;   // Wq = Win rows [0,256)
    const float* Bm = blockIdx.z ? Wao : Ws;
    float* C        = blockIdx.z ? g_W1ao : g_Wqs;
    gemm_body<false, false>(A, Bm, nullptr, C, kH, kH, kH, blockIdx.x, blockIdx.y);
}

// Composed biases: bqs = Wq@bs + bq ;  b1ao = W1@bao + b1
__global__ void __launch_bounds__(256) bias_compose_k(
    const float* __restrict__ Win, const float* __restrict__ bin,
    const float* __restrict__ bs,
    const float* __restrict__ W1,  const float* __restrict__ bao,
    const float* __restrict__ b1)
{
    __shared__ float v[kH];
    const int i = threadIdx.x;
    const float* W;
    const float* badd;
    float* outp;
    if (blockIdx.x == 0) { v[i] = bs[i];  W = Win; badd = bin; outp = g_bqs;  }
    else                 { v[i] = bao[i]; W = W1;  badd = b1;  outp = g_b1ao; }
    __syncthreads();
    float a = 0.f;
#pragma unroll 8
    for (int m = 0; m < kH; m++) a += W[i * kH + m] * v[m];
    outp[i] = a + badd[i];
}

// ---------------------------------------------------------------------------
// Fused attention: block = (n-tile of 128, head, batch), 128 threads.
// K/V tiles for (b,h) live in smem (24 KB); one q row per thread; online
// softmax fully in registers (all smem reads are warp-uniform broadcasts).
// ---------------------------------------------------------------------------
__global__ void __launch_bounds__(128) attn_k()
{
    const int b  = blockIdx.z;
    const int h  = blockIdx.y;
    const int n0 = blockIdx.x * 128;
    const int tid = threadIdx.x;

    __shared__ float ks[kS * kHD];
    __shared__ float vs[kS * kHD];

    // load K/V tile for this (b,h): 96 x 32 each
    for (int t = tid; t < kS * 8; t += 128) {
        const int s  = t >> 3;
        const int d4 = (t & 7) << 2;
        const float* row = &g_kv[(b * kS + s) * (2 * kH) + h * kHD];
        *(float4*)&ks[s * kHD + d4] = *(const float4*)&row[d4];
        *(float4*)&vs[s * kHD + d4] = *(const float4*)&row[kH + d4];
    }

    const int n = n0 + tid;
    const float* qrow = &g_q[(b * kN + n) * kH + h * kHD];
    constexpr float scale = 0.17677669529663687f;   // 1/sqrt(32)

    float q[kHD];
#pragma unroll
    for (int d4 = 0; d4 < 8; d4++) {
        const float4 t4 = *(const float4*)&qrow[d4 << 2];
        q[(d4 << 2) + 0] = t4.x * scale;
        q[(d4 << 2) + 1] = t4.y * scale;
        q[(d4 << 2) + 2] = t4.z * scale;
        q[(d4 << 2) + 3] = t4.w * scale;
    }
    __syncthreads();

    float m = -1e30f, l = 0.f;
    float acc[kHD];
#pragma unroll
    for (int d = 0; d < kHD; d++) acc[d] = 0.f;

    for (int c = 0; c < kS / 16; c++) {       // 6 chunks of 16 keys
        float lg[16];
#pragma unroll
        for (int i = 0; i < 16; i++) {
            const float* kr = &ks[(c * 16 + i) * kHD];
            float s0 = 0.f, s1 = 0.f, s2 = 0.f, s3 = 0.f;
#pragma unroll
            for (int d4 = 0; d4 < 8; d4++) {
                const float4 kk = *(const float4*)&kr[d4 << 2];
                s0 += q[(d4 << 2) + 0] * kk.x;
                s1 += q[(d4 << 2) + 1] * kk.y;
                s2 += q[(d4 << 2) + 2] * kk.z;
                s3 += q[(d4 << 2) + 3] * kk.w;
            }
            lg[i] = (s0 + s1) + (s2 + s3);
        }
        float cm = lg[0];
#pragma unroll
        for (int i = 1; i < 16; i++) cm = fmaxf(cm, lg[i]);
        const float nm   = fmaxf(m, cm);
        const float corr = __expf(m - nm);
        l *= corr;
#pragma unroll
        for (int d = 0; d < kHD; d++) acc[d] *= corr;

#pragma unroll
        for (int i = 0; i < 16; i++) {
            const float p = __expf(lg[i] - nm);
            l += p;
            const float* vr = &vs[(c * 16 + i) * kHD];
#pragma unroll
            for (int d4 = 0; d4 < 8; d4++) {
                const float4 vv = *(const float4*)&vr[d4 << 2];
                acc[(d4 << 2) + 0] += p * vv.x;
                acc[(d4 << 2) + 1] += p * vv.y;
                acc[(d4 << 2) + 2] += p * vv.z;
                acc[(d4 << 2) + 3] += p * vv.w;
            }
        }
        m = nm;
    }

    const float inv = 1.f / l;
    float* orow = &g_ctx[(b * kN + n) * kH + h * kHD];
#pragma unroll
    for (int d4 = 0; d4 < 8; d4++) {
        float4 o;
        o.x = acc[(d4 << 2) + 0] * inv;
        o.y = acc[(d4 << 2) + 1] * inv;
        o.z = acc[(d4 << 2) + 2] * inv;
        o.w = acc[(d4 << 2) + 3] * inv;
        *(float4*)&orow[d4 << 2] = o;
    }
}

// ---------------------------------------------------------------------------
// y = h2 @ Wo2^T + bo2   (4096 x 4, K=128); one row per thread
// ---------------------------------------------------------------------------
__global__ void __launch_bounds__(128) y_k(
    const float* __restrict__ Wo2, const float* __restrict__ bo2)
{
    __shared__ float w[kOUT][kH / 2];
    const int tid = threadIdx.x;
    for (int t = tid; t < kOUT * (kH / 2); t += 128)
        w[t >> 7][t & 127] = Wo2[t];
    __syncthreads();

    const int r = blockIdx.x * 128 + tid;
    const float* hrow = &g_h2[r * (kH / 2)];
    float a0 = bo2[0], a1 = bo2[1], a2 = bo2[2], a3 = bo2[3];
#pragma unroll 8
    for (int i = 0; i < kH / 2; i += 4) {
        const float4 hv = *(const float4*)&hrow[i];
        a0 += hv.x * w[0][i] + hv.y * w[0][i + 1] + hv.z * w[0][i + 2] + hv.w * w[0][i + 3];
        a1 += hv.x * w[1][i] + hv.y * w[1][i + 1] + hv.z * w[1][i + 2] + hv.w * w[1][i + 3];
        a2 += hv.x * w[2][i] + hv.y * w[2][i + 1] + hv.z * w[2][i + 2] + hv.w * w[2][i + 3];
        a3 += hv.x * w[3][i] + hv.y * w[3][i + 1] + hv.z * w[3][i + 2] + hv.w * w[3][i + 3];
    }
    *(float4*)&g_y[r * kOUT] = make_float4(a0, a1, a2, a3);
}

// ---------------------------------------------------------------------------
// out[b,s,n,:] = y[b,n,:]   (float4 per thread)
// ---------------------------------------------------------------------------
__global__ void __launch_bounds__(256) bcast_k(float4* __restrict__ out)
{
    const int idx = blockIdx.x * 256 + threadIdx.x;   // < B*S*N = 393216
    const int n  = idx & (kN - 1);
    const int bs = idx >> 9;           // b*96+s
    const int b  = bs / kS;
    out[idx] = *(const float4*)&g_y[(b * kN + n) * kOUT];
}

// ---------------------------------------------------------------------------
// kernel_launch
// ---------------------------------------------------------------------------
extern "C" void kernel_launch(void* const* d_in, const int* in_sizes, int n_in,
                              void* d_out, int out_size)
{
    const float* spatial  = (const float*)d_in[0];
    const float* temporal = (const float*)d_in[1];
    const float* Ws  = (const float*)d_in[2];
    const float* bs  = (const float*)d_in[3];
    const float* Wt  = (const float*)d_in[4];
    const float* bt  = (const float*)d_in[5];
    const float* Win = (const float*)d_in[6];
    const float* bin = (const float*)d_in[7];
    const float* Wao = (const float*)d_in[8];
    const float* bao = (const float*)d_in[9];
    const float* W1  = (const float*)d_in[10];
    const float* b1  = (const float*)d_in[11];
    const float* Wo1 = (const float*)d_in[12];
    const float* bo1 = (const float*)d_in[13];
    const float* Wo2 = (const float*)d_in[14];
    const float* bo2 = (const float*)d_in[15];

    float *pWqs, *pW1ao, *pbqs, *pb1ao, *pq, *ptp, *pkv, *pctx, *pfused, *ph2;
    cudaGetSymbolAddress((void**)&pWqs,   g_Wqs);
    cudaGetSymbolAddress((void**)&pW1ao,  g_W1ao);
    cudaGetSymbolAddress((void**)&pbqs,   g_bqs);
    cudaGetSymbolAddress((void**)&pb1ao,  g_b1ao);
    cudaGetSymbolAddress((void**)&pq,     g_q);
    cudaGetSymbolAddress((void**)&ptp,    g_tp);
    cudaGetSymbolAddress((void**)&pkv,    g_kv);
    cudaGetSymbolAddress((void**)&pctx,   g_ctx);
    cudaGetSymbolAddress((void**)&pfused, g_fused);
    cudaGetSymbolAddress((void**)&ph2,    g_h2);

    // 1. composed weights + biases
    compose_k<<<dim3(4, 4, 2), 256>>>(Win, Ws, W1, Wao);
    bias_compose_k<<<2, 256>>>(Win, bin, bs, W1, bao, b1);

    // 2. q = spatial @ Wqs^T + bqs        (4096 x 256, K=256)
    gemm_k<true, false><<<dim3(kH / 64, MQ / 64), 256>>>(spatial, pWqs, pbqs, pq, MQ, kH, kH);

    // 3. tp = temporal @ Wt^T + bt        (768 x 256)
    gemm_k<true, false><<<dim3(kH / 64, MT / 64), 256>>>(temporal, Wt, bt, ptp, MT, kH, kH);

    // 4. kv = tp @ [Wk;Wv]^T + [bk;bv]    (768 x 512) — Win rows [256,768)
    gemm_k<true, false><<<dim3(2 * kH / 64, MT / 64), 256>>>(ptp, Win + kH * kH, bin + kH,
                                                             pkv, MT, 2 * kH, kH);

    // 5. attention -> ctx (4096 x 256)
    attn_k<<<dim3(kN / 128, kNH, kB), 128>>>();

    // 6. fused = relu(ctx @ W1ao^T + b1ao)   (4096 x 256)
    gemm_k<true, true><<<dim3(kH / 64, MQ / 64), 256>>>(pctx, pW1ao, pb1ao, pfused, MQ, kH, kH);

    // 7. h2 = relu(fused @ Wo1^T + bo1)      (4096 x 128)
    gemm_k<true, true><<<dim3((kH / 2) / 64, MQ / 64), 256>>>(pfused, Wo1, bo1, ph2,
                                                              MQ, kH / 2, kH);

    // 8. y = h2 @ Wo2^T + bo2                (4096 x 4)
    y_k<<<MQ / 128, 128>>>(Wo2, bo2);

    // 9. broadcast to (B,S,N,4)
    bcast_k<<<(kB * kS * kN) / 256, 256>>>((float4*)d_out);
}

// round 5
// speedup vs baseline: 1.1930x; 1.1930x over previous
#include <cuda_runtime.h>

// ---------------------------------------------------------------------------
// Problem constants
// ---------------------------------------------------------------------------
namespace {
constexpr int kB  = 8;
constexpr int kN  = 512;
constexpr int kS  = 96;
constexpr int kH  = 256;
constexpr int kNH = 8;
constexpr int kHD = 32;
constexpr int kOUT = 4;
constexpr int MQ = kB * kN;   // 4096 query rows
constexpr int MT = kB * kS;   // 768 temporal rows
}

// ---------------------------------------------------------------------------
// Scratch (device globals — no allocation allowed)
// ---------------------------------------------------------------------------
__device__ __align__(16) float g_Wqs[kH * kH];        // Wq @ Ws
__device__ __align__(16) float g_Wkvt[2 * kH * kH];   // [Wk;Wv] @ Wt
__device__ __align__(16) float g_W1ao[kH * kH];       // W1 @ Wao
__device__ __align__(16) float g_bqs[kH];
__device__ __align__(16) float g_bkvt[2 * kH];
__device__ __align__(16) float g_b1ao[kH];
__device__ __align__(16) float g_q[MQ * kH];
__device__ __align__(16) float g_kv[MT * 2 * kH];     // [..,0:256]=k, [..,256:512]=v
__device__ __align__(16) float g_ctx[MQ * kH];
__device__ __align__(16) float g_fused[MQ * kH];
__device__ __align__(16) float g_h2[MQ * (kH / 2)];

// ---------------------------------------------------------------------------
// Register-tiled SGEMM body: C[M,N] = A[M,K] @ op(B) + bias, optional ReLU
//   BT = true :  op(B) = B^T with B stored row-major [N,K]   (NT)
//   BT = false:  op(B) = B   with B stored row-major [K,N]   (NN)
// 64x64 block tile, BK=16, 256 threads, 4x4 per thread.
// Requires M%64==0, N%64==0, K%16==0 (all call sites satisfy this).
// ---------------------------------------------------------------------------
template <bool BT, bool RELU>
__device__ __forceinline__ void gemm_body(
    const float* __restrict__ A, const float* __restrict__ Bm,
    const float* __restrict__ bias, float* __restrict__ C,
    int M, int N, int K, int bx, int by)
{
    __shared__ float As[16][64];
    __shared__ float Bs[16][64];

    const int tid = threadIdx.x;
    const int tx  = tid & 15;
    const int ty  = tid >> 4;
    const int m0  = by * 64;
    const int n0  = bx * 64;

    const int aRow = tid >> 2;          // 0..63
    const int aK   = (tid & 3) << 2;    // 0,4,8,12
    const int bKnn = tid >> 4;          // 0..15   (NN)
    const int bNnn = (tid & 15) << 2;   // 0..60   (NN)

    const float* Aptr = A + (m0 + aRow) * K + aK;
    const float* Bptr = BT ? (Bm + (n0 + aRow) * K + aK)
                           : (Bm + bKnn * N + n0 + bNnn);
    const int Bstep = BT ? 16 : 16 * N;

    float acc[4][4];
#pragma unroll
    for (int i = 0; i < 4; i++)
#pragma unroll
        for (int j = 0; j < 4; j++) acc[i][j] = 0.f;

    float4 aR = *(const float4*)Aptr;
    float4 bR = *(const float4*)Bptr;

    for (int k0 = 0;;) {
        As[aK + 0][aRow] = aR.x;
        As[aK + 1][aRow] = aR.y;
        As[aK + 2][aRow] = aR.z;
        As[aK + 3][aRow] = aR.w;
        if (BT) {
            Bs[aK + 0][aRow] = bR.x;
            Bs[aK + 1][aRow] = bR.y;
            Bs[aK + 2][aRow] = bR.z;
            Bs[aK + 3][aRow] = bR.w;
        } else {
            *(float4*)&Bs[bKnn][bNnn] = bR;
        }
        __syncthreads();

        k0 += 16;
        const bool nxt = k0 < K;
        float4 aN = make_float4(0.f, 0.f, 0.f, 0.f);
        float4 bN = make_float4(0.f, 0.f, 0.f, 0.f);
        if (nxt) {
            Aptr += 16;
            Bptr += Bstep;
            aN = *(const float4*)Aptr;
            bN = *(const float4*)Bptr;
        }

#pragma unroll
        for (int kk = 0; kk < 16; kk++) {
            const float4 av = *(const float4*)&As[kk][ty << 2];
            const float4 bv = *(const float4*)&Bs[kk][tx << 2];
            const float a[4] = {av.x, av.y, av.z, av.w};
            const float b[4] = {bv.x, bv.y, bv.z, bv.w};
#pragma unroll
            for (int i = 0; i < 4; i++)
#pragma unroll
                for (int j = 0; j < 4; j++) acc[i][j] += a[i] * b[j];
        }

        if (!nxt) break;
        __syncthreads();
        aR = aN;
        bR = bN;
    }

    float bv[4] = {0.f, 0.f, 0.f, 0.f};
    if (bias) {
        const float4 t = *(const float4*)&bias[n0 + (tx << 2)];
        bv[0] = t.x; bv[1] = t.y; bv[2] = t.z; bv[3] = t.w;
    }
#pragma unroll
    for (int i = 0; i < 4; i++) {
        const int row = m0 + (ty << 2) + i;
        float4 o;
        o.x = acc[i][0] + bv[0];
        o.y = acc[i][1] + bv[1];
        o.z = acc[i][2] + bv[2];
        o.w = acc[i][3] + bv[3];
        if (RELU) {
            o.x = fmaxf(o.x, 0.f);
            o.y = fmaxf(o.y, 0.f);
            o.z = fmaxf(o.z, 0.f);
            o.w = fmaxf(o.w, 0.f);
        }
        *(float4*)&C[row * N + n0 + (tx << 2)] = o;
    }
}

template <bool BT, bool RELU>
__global__ void __launch_bounds__(256) gemm_k(
    const float* __restrict__ A, const float* __restrict__ Bm,
    const float* __restrict__ bias, float* __restrict__ C,
    int M, int N, int K)
{
    gemm_body<BT, RELU>(A, Bm, bias, C, M, N, K, blockIdx.x, blockIdx.y);
}

// ---------------------------------------------------------------------------
// Prologue: ALL weight/bias composes in one launch (68 blocks, one wave).
//   blocks  0..15 : Wqs  = Wq  @ Ws           (256x256)
//   blocks 16..47 : Wkvt = [Wk;Wv] @ Wt       (512x256)
//   blocks 48..63 : W1ao = W1 @ Wao           (256x256)
//   blocks 64..67 : composed biases
// ---------------------------------------------------------------------------
__global__ void __launch_bounds__(256) prologue_k(
    const float* __restrict__ Win, const float* __restrict__ bin,
    const float* __restrict__ Ws,  const float* __restrict__ bs,
    const float* __restrict__ Wt,  const float* __restrict__ bt,
    const float* __restrict__ W1,  const float* __restrict__ Wao,
    const float* __restrict__ bao, const float* __restrict__ b1)
{
    const int bid = blockIdx.x;
    if (bid < 16) {
        gemm_body<false, false>(Win, Ws, nullptr, g_Wqs, kH, kH, kH, bid & 3, bid >> 2);
    } else if (bid < 48) {
        const int t = bid - 16;
        gemm_body<false, false>(Win + kH * kH, Wt, nullptr, g_Wkvt,
                                2 * kH, kH, kH, t & 3, t >> 2);
    } else if (bid < 64) {
        const int t = bid - 48;
        gemm_body<false, false>(W1, Wao, nullptr, g_W1ao, kH, kH, kH, t & 3, t >> 2);
    } else {
        __shared__ float v[kH];
        const int i = threadIdx.x;
        const float* W;
        const float* badd;
        const float* vec;
        float* outp;
        if (bid == 64)      { vec = bs;  W = Win;              badd = bin;          outp = g_bqs;        }
        else if (bid == 65) { vec = bt;  W = Win + kH * kH;    badd = bin + kH;     outp = g_bkvt;       }
        else if (bid == 66) { vec = bt;  W = Win + 2 * kH * kH; badd = bin + 2 * kH; outp = g_bkvt + kH; }
        else                { vec = bao; W = W1;               badd = b1;           outp = g_b1ao;       }
        v[i] = vec[i];
        __syncthreads();
        float a = 0.f;
#pragma unroll 8
        for (int m = 0; m < kH; m++) a += W[i * kH + m] * v[m];
        outp[i] = a + badd[i];
    }
}

// ---------------------------------------------------------------------------
// q + kv projections in ONE launch (352 blocks):
//   blocks   0..255 : q  = spatial  @ Wqs^T  + bqs    (4096 x 256, K=256)
//   blocks 256..351 : kv = temporal @ Wkvt^T + bkvt   ( 768 x 512, K=256)
// ---------------------------------------------------------------------------
__global__ void __launch_bounds__(256) qkv_k(
    const float* __restrict__ spatial, const float* __restrict__ temporal)
{
    const int bid = blockIdx.x;
    if (bid < 256) {
        gemm_body<true, false>(spatial, g_Wqs, g_bqs, g_q, MQ, kH, kH,
                               bid & 3, bid >> 2);
    } else {
        const int t = bid - 256;   // 0..95
        gemm_body<true, false>(temporal, g_Wkvt, g_bkvt, g_kv, MT, 2 * kH, kH,
                               t & 7, t >> 3);
    }
}

// ---------------------------------------------------------------------------
// Fused attention: block = (n-tile of 128, head, batch), 128 threads.
// ---------------------------------------------------------------------------
__global__ void __launch_bounds__(128) attn_k()
{
    const int b  = blockIdx.z;
    const int h  = blockIdx.y;
    const int n0 = blockIdx.x * 128;
    const int tid = threadIdx.x;

    __shared__ float ks[kS * kHD];
    __shared__ float vs[kS * kHD];

    for (int t = tid; t < kS * 8; t += 128) {
        const int s  = t >> 3;
        const int d4 = (t & 7) << 2;
        const float* row = &g_kv[(b * kS + s) * (2 * kH) + h * kHD];
        *(float4*)&ks[s * kHD + d4] = *(const float4*)&row[d4];
        *(float4*)&vs[s * kHD + d4] = *(const float4*)&row[kH + d4];
    }

    const int n = n0 + tid;
    const float* qrow = &g_q[(b * kN + n) * kH + h * kHD];
    constexpr float scale = 0.17677669529663687f;   // 1/sqrt(32)

    float q[kHD];
#pragma unroll
    for (int d4 = 0; d4 < 8; d4++) {
        const float4 t4 = *(const float4*)&qrow[d4 << 2];
        q[(d4 << 2) + 0] = t4.x * scale;
        q[(d4 << 2) + 1] = t4.y * scale;
        q[(d4 << 2) + 2] = t4.z * scale;
        q[(d4 << 2) + 3] = t4.w * scale;
    }
    __syncthreads();

    float m = -1e30f, l = 0.f;
    float acc[kHD];
#pragma unroll
    for (int d = 0; d < kHD; d++) acc[d] = 0.f;

    for (int c = 0; c < kS / 16; c++) {       // 6 chunks of 16 keys
        float lg[16];
#pragma unroll
        for (int i = 0; i < 16; i++) {
            const float* kr = &ks[(c * 16 + i) * kHD];
            float s0 = 0.f, s1 = 0.f, s2 = 0.f, s3 = 0.f;
#pragma unroll
            for (int d4 = 0; d4 < 8; d4++) {
                const float4 kk = *(const float4*)&kr[d4 << 2];
                s0 += q[(d4 << 2) + 0] * kk.x;
                s1 += q[(d4 << 2) + 1] * kk.y;
                s2 += q[(d4 << 2) + 2] * kk.z;
                s3 += q[(d4 << 2) + 3] * kk.w;
            }
            lg[i] = (s0 + s1) + (s2 + s3);
        }
        float cm = lg[0];
#pragma unroll
        for (int i = 1; i < 16; i++) cm = fmaxf(cm, lg[i]);
        const float nm   = fmaxf(m, cm);
        const float corr = __expf(m - nm);
        l *= corr;
#pragma unroll
        for (int d = 0; d < kHD; d++) acc[d] *= corr;

#pragma unroll
        for (int i = 0; i < 16; i++) {
            const float p = __expf(lg[i] - nm);
            l += p;
            const float* vr = &vs[(c * 16 + i) * kHD];
#pragma unroll
            for (int d4 = 0; d4 < 8; d4++) {
                const float4 vv = *(const float4*)&vr[d4 << 2];
                acc[(d4 << 2) + 0] += p * vv.x;
                acc[(d4 << 2) + 1] += p * vv.y;
                acc[(d4 << 2) + 2] += p * vv.z;
                acc[(d4 << 2) + 3] += p * vv.w;
            }
        }
        m = nm;
    }

    const float inv = 1.f / l;
    float* orow = &g_ctx[(b * kN + n) * kH + h * kHD];
#pragma unroll
    for (int d4 = 0; d4 < 8; d4++) {
        float4 o;
        o.x = acc[(d4 << 2) + 0] * inv;
        o.y = acc[(d4 << 2) + 1] * inv;
        o.z = acc[(d4 << 2) + 2] * inv;
        o.w = acc[(d4 << 2) + 3] * inv;
        *(float4*)&orow[d4 << 2] = o;
    }
}

// ---------------------------------------------------------------------------
// y = h2 @ Wo2^T + bo2 fused with broadcast write to (B,S,N,OUT).
// grid = (n-tiles of 128, s-chunks of 8, b); y recomputed per s-chunk (cheap).
// ---------------------------------------------------------------------------
__global__ void __launch_bounds__(128) ybcast_k(
    const float* __restrict__ Wo2, const float* __restrict__ bo2,
    float4* __restrict__ out)
{
    __shared__ float w[kOUT][kH / 2];
    const int tid = threadIdx.x;
    for (int t = tid; t < kOUT * (kH / 2); t += 128)
        w[t >> 7][t & 127] = Wo2[t];
    __syncthreads();

    const int b  = blockIdx.z;
    const int s0 = blockIdx.y * 8;
    const int n  = blockIdx.x * 128 + tid;

    const float* hrow = &g_h2[(b * kN + n) * (kH / 2)];
    float a0 = bo2[0], a1 = bo2[1], a2 = bo2[2], a3 = bo2[3];
#pragma unroll 8
    for (int i = 0; i < kH / 2; i += 4) {
        const float4 hv = *(const float4*)&hrow[i];
        a0 += hv.x * w[0][i] + hv.y * w[0][i + 1] + hv.z * w[0][i + 2] + hv.w * w[0][i + 3];
        a1 += hv.x * w[1][i] + hv.y * w[1][i + 1] + hv.z * w[1][i + 2] + hv.w * w[1][i + 3];
        a2 += hv.x * w[2][i] + hv.y * w[2][i + 1] + hv.z * w[2][i + 2] + hv.w * w[2][i + 3];
        a3 += hv.x * w[3][i] + hv.y * w[3][i + 1] + hv.z * w[3][i + 2] + hv.w * w[3][i + 3];
    }
    const float4 y4 = make_float4(a0, a1, a2, a3);

#pragma unroll
    for (int s = 0; s < 8; s++)
        out[((b * kS + s0 + s) * kN) + n] = y4;
}

// ---------------------------------------------------------------------------
// kernel_launch
// ---------------------------------------------------------------------------
extern "C" void kernel_launch(void* const* d_in, const int* in_sizes, int n_in,
                              void* d_out, int out_size)
{
    const float* spatial  = (const float*)d_in[0];
    const float* temporal = (const float*)d_in[1];
    const float* Ws  = (const float*)d_in[2];
    const float* bs  = (const float*)d_in[3];
    const float* Wt  = (const float*)d_in[4];
    const float* bt  = (const float*)d_in[5];
    const float* Win = (const float*)d_in[6];
    const float* bin = (const float*)d_in[7];
    const float* Wao = (const float*)d_in[8];
    const float* bao = (const float*)d_in[9];
    const float* W1  = (const float*)d_in[10];
    const float* b1  = (const float*)d_in[11];
    const float* Wo1 = (const float*)d_in[12];
    const float* bo1 = (const float*)d_in[13];
    const float* Wo2 = (const float*)d_in[14];
    const float* bo2 = (const float*)d_in[15];

    float *pW1ao, *pb1ao, *pctx, *pfused, *ph2;
    cudaGetSymbolAddress((void**)&pW1ao,  g_W1ao);
    cudaGetSymbolAddress((void**)&pb1ao,  g_b1ao);
    cudaGetSymbolAddress((void**)&pctx,   g_ctx);
    cudaGetSymbolAddress((void**)&pfused, g_fused);
    cudaGetSymbolAddress((void**)&ph2,    g_h2);

    // 1. all weight & bias composes (one wave)
    prologue_k<<<68, 256>>>(Win, bin, Ws, bs, Wt, bt, W1, Wao, bao, b1);

    // 2. q + kv projections (one launch, 352 blocks)
    qkv_k<<<352, 256>>>(spatial, temporal);

    // 3. attention -> ctx (4096 x 256)
    attn_k<<<dim3(kN / 128, kNH, kB), 128>>>();

    // 4. fused = relu(ctx @ W1ao^T + b1ao)   (4096 x 256)
    gemm_k<true, true><<<dim3(kH / 64, MQ / 64), 256>>>(pctx, pW1ao, pb1ao, pfused, MQ, kH, kH);

    // 5. h2 = relu(fused @ Wo1^T + bo1)      (4096 x 128)
    gemm_k<true, true><<<dim3((kH / 2) / 64, MQ / 64), 256>>>(pfused, Wo1, bo1, ph2,
                                                              MQ, kH / 2, kH);

    // 6. y = h2 @ Wo2^T + bo2, broadcast to (B,S,N,4)
    ybcast_k<<<dim3(kN / 128, kS / 8, kB), 128>>>(Wo2, bo2, (float4*)d_out);
}

// round 8
// speedup vs baseline: 1.1952x; 1.0019x over previous
#include <cuda_runtime.h>

// ---------------------------------------------------------------------------
// Problem constants
// ---------------------------------------------------------------------------
namespace {
constexpr int kB  = 8;
constexpr int kN  = 512;
constexpr int kS  = 96;
constexpr int kH  = 256;
constexpr int kNH = 8;
constexpr int kHD = 32;
constexpr int kOUT = 4;
constexpr int MQ = kB * kN;   // 4096 query rows
constexpr int MT = kB * kS;   // 768 temporal rows
}

// ---------------------------------------------------------------------------
// Scratch (device globals — no allocation allowed)
// ---------------------------------------------------------------------------
__device__ __align__(16) float g_Wqs[kH * kH];        // Wq @ Ws
__device__ __align__(16) float g_Wkvt[2 * kH * kH];   // [Wk;Wv] @ Wt
__device__ __align__(16) float g_W1ao[kH * kH];       // W1 @ Wao
__device__ __align__(16) float g_bqs[kH];
__device__ __align__(16) float g_bkvt[2 * kH];
__device__ __align__(16) float g_b1ao[kH];
__device__ __align__(16) float g_q[MQ * kH];
__device__ __align__(16) float g_kv[MT * 2 * kH];     // [..,0:256]=k, [..,256:512]=v
__device__ __align__(16) float g_ctx[MQ * kH];
__device__ __align__(16) float g_fused[MQ * kH];
__device__ __align__(16) float g_h2[MQ * (kH / 2)];

// ---------------------------------------------------------------------------
// Register-tiled SGEMM body: C[M,N] = A[M,K] @ op(B) + bias, optional ReLU
//   BT = true :  op(B) = B^T with B stored row-major [N,K]   (NT)
//   BT = false:  op(B) = B   with B stored row-major [K,N]   (NN)
// 64x64 block tile, BK=16, 128 threads, 8x4 per thread, double-buffered smem.
// Requires M%64==0, N%64==0, K%16==0, K>=32 (all call sites satisfy this).
// ---------------------------------------------------------------------------
template <bool BT, bool RELU>
__device__ __forceinline__ void gemm_body(
    const float* __restrict__ A, const float* __restrict__ Bm,
    const float* __restrict__ bias, float* __restrict__ C,
    int M, int N, int K, int bx, int by)
{
    __shared__ float As[2][16][64];
    __shared__ float Bs[2][16][64];

    const int tid = threadIdx.x;       // 0..127
    const int tx  = tid & 15;          // col group: cols n0 + tx*4 .. +3
    const int ty  = tid >> 4;          // row group: rows m0 + ty*8 .. +7
    const int m0  = by * 64;
    const int n0  = bx * 64;

    // Loader mapping: lane = row (conflict-free scalar STS), warp = k-quarter.
    const int lr = tid & 31;           // row within half-tile (0..31)
    const int lk = (tid >> 5) << 2;    // k offset: 0,4,8,12

    const float* Aptr = A + (m0 + lr) * K + lk;
    const float* Bptr = BT ? (Bm + (n0 + lr) * K + lk)
                           : (Bm + (tid >> 4) * N + n0 + ((tid & 15) << 2));

    float4 a0R = *(const float4*)Aptr;
    float4 a1R = *(const float4*)(Aptr + 32 * K);
    float4 b0R, b1R;
    if (BT) {
        b0R = *(const float4*)Bptr;
        b1R = *(const float4*)(Bptr + 32 * K);
    } else {
        b0R = *(const float4*)Bptr;
        b1R = *(const float4*)(Bptr + 8 * N);
    }

    float acc[8][4];
#pragma unroll
    for (int i = 0; i < 8; i++)
#pragma unroll
        for (int j = 0; j < 4; j++) acc[i][j] = 0.f;

    // stage 0 store
    {
        As[0][lk + 0][lr] = a0R.x;
        As[0][lk + 1][lr] = a0R.y;
        As[0][lk + 2][lr] = a0R.z;
        As[0][lk + 3][lr] = a0R.w;
        As[0][lk + 0][lr + 32] = a1R.x;
        As[0][lk + 1][lr + 32] = a1R.y;
        As[0][lk + 2][lr + 32] = a1R.z;
        As[0][lk + 3][lr + 32] = a1R.w;
        if (BT) {
            Bs[0][lk + 0][lr] = b0R.x;
            Bs[0][lk + 1][lr] = b0R.y;
            Bs[0][lk + 2][lr] = b0R.z;
            Bs[0][lk + 3][lr] = b0R.w;
            Bs[0][lk + 0][lr + 32] = b1R.x;
            Bs[0][lk + 1][lr + 32] = b1R.y;
            Bs[0][lk + 2][lr + 32] = b1R.z;
            Bs[0][lk + 3][lr + 32] = b1R.w;
        } else {
            *(float4*)&Bs[0][tid >> 4][(tid & 15) << 2] = b0R;
            *(float4*)&Bs[0][(tid >> 4) + 8][(tid & 15) << 2] = b1R;
        }
    }
    __syncthreads();

    int s = 0;
    for (int k0 = 16;; k0 += 16) {
        const bool nxt = (k0 < K);
        if (nxt) {
            Aptr += 16;
            Bptr += BT ? 16 : 16 * N;
            a0R = *(const float4*)Aptr;
            a1R = *(const float4*)(Aptr + 32 * K);
            if (BT) {
                b0R = *(const float4*)Bptr;
                b1R = *(const float4*)(Bptr + 32 * K);
            } else {
                b0R = *(const float4*)Bptr;
                b1R = *(const float4*)(Bptr + 8 * N);
            }
        }

#pragma unroll
        for (int kk = 0; kk < 16; kk++) {
            const float4 b4  = *(const float4*)&Bs[s][kk][tx << 2];
            const float4 alo = *(const float4*)&As[s][kk][ty << 3];
            const float4 ahi = *(const float4*)&As[s][kk][(ty << 3) + 4];
            const float a[8] = {alo.x, alo.y, alo.z, alo.w, ahi.x, ahi.y, ahi.z, ahi.w};
            const float b[4] = {b4.x, b4.y, b4.z, b4.w};
#pragma unroll
            for (int i = 0; i < 8; i++)
#pragma unroll
                for (int j = 0; j < 4; j++) acc[i][j] += a[i] * b[j];
        }

        if (!nxt) break;

        const int d = s ^ 1;
        As[d][lk + 0][lr] = a0R.x;
        As[d][lk + 1][lr] = a0R.y;
        As[d][lk + 2][lr] = a0R.z;
        As[d][lk + 3][lr] = a0R.w;
        As[d][lk + 0][lr + 32] = a1R.x;
        As[d][lk + 1][lr + 32] = a1R.y;
        As[d][lk + 2][lr + 32] = a1R.z;
        As[d][lk + 3][lr + 32] = a1R.w;
        if (BT) {
            Bs[d][lk + 0][lr] = b0R.x;
            Bs[d][lk + 1][lr] = b0R.y;
            Bs[d][lk + 2][lr] = b0R.z;
            Bs[d][lk + 3][lr] = b0R.w;
            Bs[d][lk + 0][lr + 32] = b1R.x;
            Bs[d][lk + 1][lr + 32] = b1R.y;
            Bs[d][lk + 2][lr + 32] = b1R.z;
            Bs[d][lk + 3][lr + 32] = b1R.w;
        } else {
            *(float4*)&Bs[d][tid >> 4][(tid & 15) << 2] = b0R;
            *(float4*)&Bs[d][(tid >> 4) + 8][(tid & 15) << 2] = b1R;
        }
        __syncthreads();
        s = d;
    }

    float bv[4] = {0.f, 0.f, 0.f, 0.f};
    if (bias) {
        const float4 t = *(const float4*)&bias[n0 + (tx << 2)];
        bv[0] = t.x; bv[1] = t.y; bv[2] = t.z; bv[3] = t.w;
    }
#pragma unroll
    for (int i = 0; i < 8; i++) {
        const int row = m0 + (ty << 3) + i;
        float4 o;
        o.x = acc[i][0] + bv[0];
        o.y = acc[i][1] + bv[1];
        o.z = acc[i][2] + bv[2];
        o.w = acc[i][3] + bv[3];
        if (RELU) {
            o.x = fmaxf(o.x, 0.f);
            o.y = fmaxf(o.y, 0.f);
            o.z = fmaxf(o.z, 0.f);
            o.w = fmaxf(o.w, 0.f);
        }
        *(float4*)&C[row * N + n0 + (tx << 2)] = o;
    }
}

template <bool BT, bool RELU>
__global__ void __launch_bounds__(128) gemm_k(
    const float* __restrict__ A, const float* __restrict__ Bm,
    const float* __restrict__ bias, float* __restrict__ C,
    int M, int N, int K)
{
    gemm_body<BT, RELU>(A, Bm, bias, C, M, N, K, blockIdx.x, blockIdx.y);
}

// ---------------------------------------------------------------------------
// Prologue: ALL weight/bias composes in one launch (68 blocks, one wave).
//   blocks  0..15 : Wqs  = Wq  @ Ws           (256x256)
//   blocks 16..47 : Wkvt = [Wk;Wv] @ Wt       (512x256)
//   blocks 48..63 : W1ao = W1 @ Wao           (256x256)
//   blocks 64..67 : composed biases
// ---------------------------------------------------------------------------
__global__ void __launch_bounds__(128) prologue_k(
    const float* __restrict__ Win, const float* __restrict__ bin,
    const float* __restrict__ Ws,  const float* __restrict__ bs,
    const float* __restrict__ Wt,  const float* __restrict__ bt,
    const float* __restrict__ W1,  const float* __restrict__ Wao,
    const float* __restrict__ bao, const float* __restrict__ b1)
{
    const int bid = blockIdx.x;
    if (bid < 16) {
        gemm_body<false, false>(Win, Ws, nullptr, g_Wqs, kH, kH, kH, bid & 3, bid >> 2);
    } else if (bid < 48) {
        const int t = bid - 16;
        gemm_body<false, false>(Win + kH * kH, Wt, nullptr, g_Wkvt,
                                2 * kH, kH, kH, t & 3, t >> 2);
    } else if (bid < 64) {
        const int t = bid - 48;
        gemm_body<false, false>(W1, Wao, nullptr, g_W1ao, kH, kH, kH, t & 3, t >> 2);
    } else {
        __shared__ float v[kH];
        const int i = threadIdx.x;          // 0..127, two outputs per thread
        const float* W;
        const float* badd;
        const float* vec;
        float* outp;
        if (bid == 64)      { vec = bs;  W = Win;               badd = bin;           outp = g_bqs;       }
        else if (bid == 65) { vec = bt;  W = Win + kH * kH;     badd = bin + kH;      outp = g_bkvt;      }
        else if (bid == 66) { vec = bt;  W = Win + 2 * kH * kH; badd = bin + 2 * kH;  outp = g_bkvt + kH; }
        else                { vec = bao; W = W1;                badd = b1;            outp = g_b1ao;      }
        v[i] = vec[i];
        v[i + 128] = vec[i + 128];
        __syncthreads();
#pragma unroll
        for (int r = 0; r < 2; r++) {
            const int o = i + r * 128;
            float a = 0.f;
#pragma unroll 8
            for (int m = 0; m < kH; m++) a += W[o * kH + m] * v[m];
            outp[o] = a + badd[o];
        }
    }
}

// ---------------------------------------------------------------------------
// q + kv projections in ONE launch (352 blocks):
//   blocks   0..255 : q  = spatial  @ Wqs^T  + bqs    (4096 x 256, K=256)
//   blocks 256..351 : kv = temporal @ Wkvt^T + bkvt   ( 768 x 512, K=256)
// ---------------------------------------------------------------------------
__global__ void __launch_bounds__(128) qkv_k(
    const float* __restrict__ spatial, const float* __restrict__ temporal)
{
    const int bid = blockIdx.x;
    if (bid < 256) {
        gemm_body<true, false>(spatial, g_Wqs, g_bqs, g_q, MQ, kH, kH,
                               bid & 3, bid >> 2);
    } else {
        const int t = bid - 256;   // 0..95
        gemm_body<true, false>(temporal, g_Wkvt, g_bkvt, g_kv, MT, 2 * kH, kH,
                               t & 7, t >> 3);
    }
}

// ---------------------------------------------------------------------------
// Fused attention: block = (n-tile of 128, head, batch), 128 threads.
// ---------------------------------------------------------------------------
__global__ void __launch_bounds__(128) attn_k()
{
    const int b  = blockIdx.z;
    const int h  = blockIdx.y;
    const int n0 = blockIdx.x * 128;
    const int tid = threadIdx.x;

    __shared__ float ks[kS * kHD];
    __shared__ float vs[kS * kHD];

    for (int t = tid; t < kS * 8; t += 128) {
        const int s  = t >> 3;
        const int d4 = (t & 7) << 2;
        const float* row = &g_kv[(b * kS + s) * (2 * kH) + h * kHD];
        *(float4*)&ks[s * kHD + d4] = *(const float4*)&row[d4];
        *(float4*)&vs[s * kHD + d4] = *(const float4*)&row[kH + d4];
    }

    const int n = n0 + tid;
    const float* qrow = &g_q[(b * kN + n) * kH + h * kHD];
    constexpr float scale = 0.17677669529663687f;   // 1/sqrt(32)

    float q[kHD];
#pragma unroll
    for (int d4 = 0; d4 < 8; d4++) {
        const float4 t4 = *(const float4*)&qrow[d4 << 2];
        q[(d4 << 2) + 0] = t4.x * scale;
        q[(d4 << 2) + 1] = t4.y * scale;
        q[(d4 << 2) + 2] = t4.z * scale;
        q[(d4 << 2) + 3] = t4.w * scale;
    }
    __syncthreads();

    float m = -1e30f, l = 0.f;
    float acc[kHD];
#pragma unroll
    for (int d = 0; d < kHD; d++) acc[d] = 0.f;

    for (int c = 0; c < kS / 16; c++) {       // 6 chunks of 16 keys
        float lg[16];
#pragma unroll
        for (int i = 0; i < 16; i++) {
            const float* kr = &ks[(c * 16 + i) * kHD];
            float s0 = 0.f, s1 = 0.f, s2 = 0.f, s3 = 0.f;
#pragma unroll
            for (int d4 = 0; d4 < 8; d4++) {
                const float4 kk = *(const float4*)&kr[d4 << 2];
                s0 += q[(d4 << 2) + 0] * kk.x;
                s1 += q[(d4 << 2) + 1] * kk.y;
                s2 += q[(d4 << 2) + 2] * kk.z;
                s3 += q[(d4 << 2) + 3] * kk.w;
            }
            lg[i] = (s0 + s1) + (s2 + s3);
        }
        float cm = lg[0];
#pragma unroll
        for (int i = 1; i < 16; i++) cm = fmaxf(cm, lg[i]);
        const float nm   = fmaxf(m, cm);
        const float corr = __expf(m - nm);
        l *= corr;
#pragma unroll
        for (int d = 0; d < kHD; d++) acc[d] *= corr;

#pragma unroll
        for (int i = 0; i < 16; i++) {
            const float p = __expf(lg[i] - nm);
            l += p;
            const float* vr = &vs[(c * 16 + i) * kHD];
#pragma unroll
            for (int d4 = 0; d4 < 8; d4++) {
                const float4 vv = *(const float4*)&vr[d4 << 2];
                acc[(d4 << 2) + 0] += p * vv.x;
                acc[(d4 << 2) + 1] += p * vv.y;
                acc[(d4 << 2) + 2] += p * vv.z;
                acc[(d4 << 2) + 3] += p * vv.w;
            }
        }
        m = nm;
    }

    const float inv = 1.f / l;
    float* orow = &g_ctx[(b * kN + n) * kH + h * kHD];
#pragma unroll
    for (int d4 = 0; d4 < 8; d4++) {
        float4 o;
        o.x = acc[(d4 << 2) + 0] * inv;
        o.y = acc[(d4 << 2) + 1] * inv;
        o.z = acc[(d4 << 2) + 2] * inv;
        o.w = acc[(d4 << 2) + 3] * inv;
        *(float4*)&orow[d4 << 2] = o;
    }
}

// ---------------------------------------------------------------------------
// y = h2 @ Wo2^T + bo2 fused with broadcast write to (B,S,N,OUT).
// grid = (n-tiles of 128, s-chunks of 8, b); y recomputed per s-chunk (cheap).
// ---------------------------------------------------------------------------
__global__ void __launch_bounds__(128) ybcast_k(
    const float* __restrict__ Wo2, const float* __restrict__ bo2,
    float4* __restrict__ out)
{
    __shared__ float w[kOUT][kH / 2];
    const int tid = threadIdx.x;
    for (int t = tid; t < kOUT * (kH / 2); t += 128)
        w[t >> 7][t & 127] = Wo2[t];
    __syncthreads();

    const int b  = blockIdx.z;
    const int s0 = blockIdx.y * 8;
    const int n  = blockIdx.x * 128 + tid;

    const float* hrow = &g_h2[(b * kN + n) * (kH / 2)];
    float a0 = bo2[0], a1 = bo2[1], a2 = bo2[2], a3 = bo2[3];
#pragma unroll 8
    for (int i = 0; i < kH / 2; i += 4) {
        const float4 hv = *(const float4*)&hrow[i];
        a0 += hv.x * w[0][i] + hv.y * w[0][i + 1] + hv.z * w[0][i + 2] + hv.w * w[0][i + 3];
        a1 += hv.x * w[1][i] + hv.y * w[1][i + 1] + hv.z * w[1][i + 2] + hv.w * w[1][i + 3];
        a2 += hv.x * w[2][i] + hv.y * w[2][i + 1] + hv.z * w[2][i + 2] + hv.w * w[2][i + 3];
        a3 += hv.x * w[3][i] + hv.y * w[3][i + 1] + hv.z * w[3][i + 2] + hv.w * w[3][i + 3];
    }
    const float4 y4 = make_float4(a0, a1, a2, a3);

#pragma unroll
    for (int s = 0; s < 8; s++)
        out[((b * kS + s0 + s) * kN) + n] = y4;
}

// ---------------------------------------------------------------------------
// kernel_launch
// ---------------------------------------------------------------------------
extern "C" void kernel_launch(void* const* d_in, const int* in_sizes, int n_in,
                              void* d_out, int out_size)
{
    const float* spatial  = (const float*)d_in[0];
    const float* temporal = (const float*)d_in[1];
    const float* Ws  = (const float*)d_in[2];
    const float* bs  = (const float*)d_in[3];
    const float* Wt  = (const float*)d_in[4];
    const float* bt  = (const float*)d_in[5];
    const float* Win = (const float*)d_in[6];
    const float* bin = (const float*)d_in[7];
    const float* Wao = (const float*)d_in[8];
    const float* bao = (const float*)d_in[9];
    const float* W1  = (const float*)d_in[10];
    const float* b1  = (const float*)d_in[11];
    const float* Wo1 = (const float*)d_in[12];
    const float* bo1 = (const float*)d_in[13];
    const float* Wo2 = (const float*)d_in[14];
    const float* bo2 = (const float*)d_in[15];

    float *pW1ao, *pb1ao, *pctx, *pfused, *ph2;
    cudaGetSymbolAddress((void**)&pW1ao,  g_W1ao);
    cudaGetSymbolAddress((void**)&pb1ao,  g_b1ao);
    cudaGetSymbolAddress((void**)&pctx,   g_ctx);
    cudaGetSymbolAddress((void**)&pfused, g_fused);
    cudaGetSymbolAddress((void**)&ph2,    g_h2);

    // 1. all weight & bias composes (one wave)
    prologue_k<<<68, 128>>>(Win, bin, Ws, bs, Wt, bt, W1, Wao, bao, b1);

    // 2. q + kv projections (one launch, 352 blocks)
    qkv_k<<<352, 128>>>(spatial, temporal);

    // 3. attention -> ctx (4096 x 256)
    attn_k<<<dim3(kN / 128, kNH, kB), 128>>>();

    // 4. fused = relu(ctx @ W1ao^T + b1ao)   (4096 x 256)
    gemm_k<true, true><<<dim3(kH / 64, MQ / 64), 128>>>(pctx, pW1ao, pb1ao, pfused, MQ, kH, kH);

    // 5. h2 = relu(fused @ Wo1^T + bo1)      (4096 x 128)
    gemm_k<true, true><<<dim3((kH / 2) / 64, MQ / 64), 128>>>(pfused, Wo1, bo1, ph2,
                                                              MQ, kH / 2, kH);

    // 6. y = h2 @ Wo2^T + bo2, broadcast to (B,S,N,4)
    ybcast_k<<<dim3(kN / 128, kS / 8, kB), 128>>>(Wo2, bo2, (float4*)d_out);
}